// round 8
// baseline (speedup 1.0000x reference)
#include <cuda_runtime.h>
#include <cuda_bf16.h>
#include <cstdint>

// RNN1: B=16384, T=256, I=5, H=2, F=128, C=1
// 128-thread blocks (4 warps -> 4 SMSPs), 32 rows/warp, lane = row.
// cp.async double-buffered staging (proven). Compute: source-level software
// pipeline — group j+1's LDS + projection FMAs are textually interleaved
// between group j's dependent STEPs, so the warp's in-order issue stream
// always has independent work inside the recurrence-chain stall shadow.
// tanh.approx for steps 0..223, exact ex2/rcp tanh for the last 32 steps.

#define NCH       8
#define F4C       40
#define RP        41
#define WTILE     (32 * RP)
#define SMEM_BYTES (4 * 2 * WTILE * 16)

__device__ __forceinline__ float ex2_approx(float x) {
    float y; asm("ex2.approx.f32 %0, %1;" : "=f"(y) : "f"(x)); return y;
}
__device__ __forceinline__ float rcp_approx(float x) {
    float y; asm("rcp.approx.f32 %0, %1;" : "=f"(y) : "f"(x)); return y;
}
__device__ __forceinline__ float tanh_fast(float x) {
    float y; asm("tanh.approx.f32 %0, %1;" : "=f"(y) : "f"(x)); return y;
}

__device__ __forceinline__ void cp_async16(unsigned int dst_smem, const void* src) {
    asm volatile("cp.async.cg.shared.global [%0], [%1], 16;\n"
                 :: "r"(dst_smem), "l"(src));
}

extern __shared__ float4 tile[];   // [4 warps][2 bufs][32 rows][41 f4]

__global__ void __launch_bounds__(128, 1) rnn1_kernel(
    const float* __restrict__ x,
    const float* __restrict__ Wih, const float* __restrict__ Whh,
    const float* __restrict__ bih, const float* __restrict__ bhh,
    const float* __restrict__ W1,  const float* __restrict__ b1,
    const float* __restrict__ W2,  const float* __restrict__ b2,
    float* __restrict__ out)
{
    const int lane = threadIdx.x & 31;
    const int wid  = threadIdx.x >> 5;
    const int warp_row0 = blockIdx.x * 128 + wid * 32;

    // UNSCALED weights (tanh.approx takes the raw argument)
    float wi0[5], wi1[5];
#pragma unroll
    for (int i = 0; i < 5; ++i) { wi0[i] = Wih[i]; wi1[i] = Wih[5 + i]; }
    const float a00 = Whh[0], a01 = Whh[1];
    const float a10 = Whh[2], a11 = Whh[3];
    const float c0 = bih[0] + bhh[0];
    const float c1 = bih[1] + bhh[1];
    const float S = 2.885390081777926815f;  // 2/ln(2), exact tail only

    const float4* __restrict__ xw =
        reinterpret_cast<const float4*>(x) + (size_t)warp_row0 * 320;

    const int grp = lane >> 3;
    const int sub = lane & 7;
    const float4* src_base = xw + grp * 320 + sub;

    const unsigned int smem0 = (unsigned int)__cvta_generic_to_shared(tile);
    const unsigned int dst0 =
        smem0 + (unsigned int)((wid * 2 * WTILE) + grp * RP + sub) * 16u;
    const unsigned int dst1 = dst0 + (unsigned int)WTILE * 16u;

    auto issue_chunk = [&](int chunk, int buf) {
        const float4* s = src_base + chunk * F4C;
        const unsigned int d = buf ? dst1 : dst0;
#pragma unroll
        for (int j = 0; j < 8; ++j)
#pragma unroll
            for (int k = 0; k < 5; ++k)
                cp_async16(d + (unsigned int)(j * 4 * RP + k * 8) * 16u,
                           s + j * 4 * 320 + k * 8);
        asm volatile("cp.async.commit_group;");
    };

    float h0 = 0.0f, h1 = 0.0f;

#define PROJ(pa, pb, x0, x1, x2, x3, x4)                               \
    do {                                                               \
        pa = fmaf(wi0[0], (x0), pa);  pb = fmaf(wi1[0], (x0), pb);     \
        pa = fmaf(wi0[1], (x1), pa);  pb = fmaf(wi1[1], (x1), pb);     \
        pa = fmaf(wi0[2], (x2), pa);  pb = fmaf(wi1[2], (x2), pb);     \
        pa = fmaf(wi0[3], (x3), pa);  pb = fmaf(wi1[3], (x3), pb);     \
        pa = fmaf(wi0[4], (x4), pa);  pb = fmaf(wi1[4], (x4), pb);     \
    } while (0)

#define STEP_A(pa, pb)                                                 \
    do {                                                               \
        float z0 = fmaf(a01, h1, fmaf(a00, h0, pa));                   \
        float z1 = fmaf(a11, h1, fmaf(a10, h0, pb));                   \
        h0 = tanh_fast(z0);                                            \
        h1 = tanh_fast(z1);                                            \
    } while (0)

#define STEP_E(pa, pb)                                                 \
    do {                                                               \
        float z0 = fmaf(a01, h1, fmaf(a00, h0, pa));                   \
        float z1 = fmaf(a11, h1, fmaf(a10, h0, pb));                   \
        float e0 = ex2_approx(S * z0);                                 \
        float e1 = ex2_approx(S * z1);                                 \
        float r0 = rcp_approx(e0 + 1.0f);                              \
        float r1 = rcp_approx(e1 + 1.0f);                              \
        h0 = fmaf(-2.0f, r0, 1.0f);                                    \
        h1 = fmaf(-2.0f, r1, 1.0f);                                    \
    } while (0)

    const float4* myrow0 = &tile[wid * 2 * WTILE + lane * RP];

    // Software-pipelined chunk: projections for group j+1 are interleaved
    // between the dependent STEPs of group j.
#define CHUNK_BODY(STEPM, buf)                                         \
    do {                                                               \
        const float4* __restrict__ myrow = myrow0 + (buf) * WTILE;     \
        float4 q0 = myrow[0], q1 = myrow[1], q2 = myrow[2],            \
               q3 = myrow[3], q4 = myrow[4];                           \
        float p00 = c0, p01 = c1, p10 = c0, p11 = c1;                  \
        float p20 = c0, p21 = c1, p30 = c0, p31 = c1;                  \
        PROJ(p00, p01, q0.x, q0.y, q0.z, q0.w, q1.x);                  \
        PROJ(p10, p11, q1.y, q1.z, q1.w, q2.x, q2.y);                  \
        PROJ(p20, p21, q2.z, q2.w, q3.x, q3.y, q3.z);                  \
        PROJ(p30, p31, q3.w, q4.x, q4.y, q4.z, q4.w);                  \
        _Pragma("unroll")                                              \
        for (int j = 0; j < 8; ++j) {                                  \
            float4 n0, n1, n2, n3, n4;                                 \
            if (j < 7) {                                               \
                n0 = myrow[5 * (j + 1) + 0];                           \
                n1 = myrow[5 * (j + 1) + 1];                           \
                n2 = myrow[5 * (j + 1) + 2];                           \
                n3 = myrow[5 * (j + 1) + 3];                           \
                n4 = myrow[5 * (j + 1) + 4];                           \
            }                                                          \
            float m00 = c0, m01 = c1, m10 = c0, m11 = c1;              \
            float m20 = c0, m21 = c1, m30 = c0, m31 = c1;              \
            STEPM(p00, p01);                                           \
            if (j < 7) PROJ(m00, m01, n0.x, n0.y, n0.z, n0.w, n1.x);   \
            STEPM(p10, p11);                                           \
            if (j < 7) PROJ(m10, m11, n1.y, n1.z, n1.w, n2.x, n2.y);   \
            STEPM(p20, p21);                                           \
            if (j < 7) PROJ(m20, m21, n2.z, n2.w, n3.x, n3.y, n3.z);   \
            STEPM(p30, p31);                                           \
            if (j < 7) {                                               \
                PROJ(m30, m31, n3.w, n4.x, n4.y, n4.z, n4.w);          \
                p00 = m00; p01 = m01; p10 = m10; p11 = m11;            \
                p20 = m20; p21 = m21; p30 = m30; p31 = m31;            \
            }                                                          \
        }                                                              \
    } while (0)

    // ---- pipeline: chunks 0..6 approx, chunk 7 exact ----
    issue_chunk(0, 0);
    issue_chunk(1, 1);

    for (int g = 0; g < NCH - 1; ++g) {             // g = 0..6 (approx)
        asm volatile("cp.async.wait_group 1;");
        __syncwarp();
        CHUNK_BODY(STEP_A, g & 1);
        if (g + 2 < NCH)
            issue_chunk(g + 2, g & 1);
    }
    asm volatile("cp.async.wait_group 0;");
    __syncwarp();
    CHUNK_BODY(STEP_E, (NCH - 1) & 1);              // last 32 steps exact
#undef PROJ
#undef STEP_A
#undef STEP_E
#undef CHUNK_BODY

    // ---- head: relu(h) -> FC(2->128) + relu -> FC(128->1) ----
    const float r0 = fmaxf(h0, 0.0f);
    const float r1 = fmaxf(h1, 0.0f);
    const float2* __restrict__ W1v = reinterpret_cast<const float2*>(W1);
    float acc = b2[0];
#pragma unroll 8
    for (int f = 0; f < 128; ++f) {
        float2 w = W1v[f];
        float t = fmaf(w.x, r0, fmaf(w.y, r1, b1[f]));
        acc = fmaf(fmaxf(t, 0.0f), W2[f], acc);
    }
    out[warp_row0 + lane] = acc;
}

extern "C" void kernel_launch(void* const* d_in, const int* in_sizes, int n_in,
                              void* d_out, int out_size)
{
    const float* x   = (const float*)d_in[0];
    const float* Wih = (const float*)d_in[1];
    const float* Whh = (const float*)d_in[2];
    const float* bih = (const float*)d_in[3];
    const float* bhh = (const float*)d_in[4];
    const float* W1  = (const float*)d_in[5];
    const float* b1  = (const float*)d_in[6];
    const float* W2  = (const float*)d_in[7];
    const float* b2  = (const float*)d_in[8];
    float* out = (float*)d_out;

    static int smem_set = 0;
    if (!smem_set) {
        cudaFuncSetAttribute(rnn1_kernel,
                             cudaFuncAttributeMaxDynamicSharedMemorySize,
                             SMEM_BYTES);
        smem_set = 1;
    }

    rnn1_kernel<<<128, 128, SMEM_BYTES>>>(x, Wih, Whh, bih, bhh,
                                          W1, b1, W2, b2, out);
}